// round 2
// baseline (speedup 1.0000x reference)
#include <cuda_runtime.h>
#include <cuda_bf16.h>
#include <cstdint>

// Problem constants
#define B_   64
#define L_   4096
#define KD_  128
#define H_   4
#define OUT_ 256

#define CHUNKS 8                 // L-chunks per batch
#define WARPS  8                 // warps per block in pass 1
#define ROWS_PER_WARP (L_ / CHUNKS / WARPS)   // 64
#define NBLK1 (B_ * CHUNKS)      // 512

// Deterministic scratch (no device allocation allowed)
__device__ float g_pacc[NBLK1][KD_ * H_];  // 512 x 512 f32 = 1 MB
__device__ float g_pZ[NBLK1][H_];

// ---------------------------------------------------------------------------
// Pass 1: streaming attention-pool partials.
// Warp-per-row; masked rows skipped entirely (they contribute exactly 0:
// exp(-1e9) == 0.0f in fp32, and 0-weight rows add nothing to pooled).
// No max-subtraction in softmax: |score| <~ 4, plain __expf is accurate.
// ---------------------------------------------------------------------------
__global__ void __launch_bounds__(256, 4)
pool_pass1(const float* __restrict__ x,
           const int* __restrict__ mask,       // bool coerced to int32 by harness
           const float* __restrict__ q)
{
    const int blk  = blockIdx.x;
    const int b    = blk / CHUNKS;
    const int c    = blk % CHUNKS;
    const int w    = threadIdx.x >> 5;
    const int lane = threadIdx.x & 31;

    // queries[h][lane*4 .. lane*4+3]
    float4 q4[H_];
#pragma unroll
    for (int h = 0; h < H_; h++)
        q4[h] = *reinterpret_cast<const float4*>(q + h * KD_ + lane * 4);

    float acc[4][H_];
#pragma unroll
    for (int j = 0; j < 4; j++)
#pragma unroll
        for (int h = 0; h < H_; h++) acc[j][h] = 0.0f;
    float Z[H_] = {0.f, 0.f, 0.f, 0.f};

    const int l0 = c * (L_ / CHUNKS) + w * ROWS_PER_WARP;
    const float* xb = x + (size_t)b * L_ * KD_;
    const int* mb = mask + (size_t)b * L_;

#pragma unroll 2
    for (int r = 0; r < ROWS_PER_WARP; r++) {
        const int l = l0 + r;
        if (mb[l] == 0) continue;   // warp-uniform: masked row contributes exactly 0

        float4 xv = *reinterpret_cast<const float4*>(xb + (size_t)l * KD_ + lane * 4);

        float s[H_];
#pragma unroll
        for (int h = 0; h < H_; h++)
            s[h] = xv.x * q4[h].x + xv.y * q4[h].y + xv.z * q4[h].z + xv.w * q4[h].w;

        // full-warp butterfly reduce per head (all lanes end with the sum)
#pragma unroll
        for (int h = 0; h < H_; h++)
#pragma unroll
            for (int off = 16; off >= 1; off >>= 1)
                s[h] += __shfl_xor_sync(0xffffffffu, s[h], off);

        float p[H_];
#pragma unroll
        for (int h = 0; h < H_; h++) { p[h] = __expf(s[h]); Z[h] += p[h]; }

        const float xj[4] = {xv.x, xv.y, xv.z, xv.w};
#pragma unroll
        for (int j = 0; j < 4; j++)
#pragma unroll
            for (int h = 0; h < H_; h++)
                acc[j][h] = fmaf(xj[j], p[h], acc[j][h]);
    }

    // Block-level deterministic reduce
    __shared__ float sAcc[WARPS][KD_ * H_];
    __shared__ float sZ[WARPS][H_];
#pragma unroll
    for (int j = 0; j < 4; j++)
#pragma unroll
        for (int h = 0; h < H_; h++)
            sAcc[w][(lane * 4 + j) * H_ + h] = acc[j][h];   // idx = k*H + h
    if (lane < H_) sZ[w][lane] = Z[lane];
    __syncthreads();

    for (int idx = threadIdx.x; idx < KD_ * H_; idx += 256) {
        float v = 0.f;
#pragma unroll
        for (int ww = 0; ww < WARPS; ww++) v += sAcc[ww][idx];
        g_pacc[blk][idx] = v;
    }
    if (threadIdx.x < H_) {
        float v = 0.f;
#pragma unroll
        for (int ww = 0; ww < WARPS; ww++) v += sZ[ww][threadIdx.x];
        g_pZ[blk][threadIdx.x] = v;
    }
}

// ---------------------------------------------------------------------------
// Pass 2: combine chunk partials -> pooled, then
//   out = relu(pooled @ W^T + b + relu(emb[num]))
// One block per batch, thread o computes output element o (256 == OUT).
// ---------------------------------------------------------------------------
__global__ void __launch_bounds__(256, 4)
pool_pass2(const float* __restrict__ W,
           const float* __restrict__ bias,
           const float* __restrict__ emb,
           const int* __restrict__ num,
           float* __restrict__ out)
{
    const int b   = blockIdx.x;
    const int tid = threadIdx.x;

    __shared__ float pooled[KD_ * H_];
    __shared__ float Zs[H_];

    for (int idx = tid; idx < KD_ * H_; idx += 256) {
        float v = 0.f;
#pragma unroll
        for (int c = 0; c < CHUNKS; c++) v += g_pacc[b * CHUNKS + c][idx];
        pooled[idx] = v;
    }
    if (tid < H_) {
        float v = 0.f;
#pragma unroll
        for (int c = 0; c < CHUNKS; c++) v += g_pZ[b * CHUNKS + c][tid];
        Zs[tid] = v;
    }
    __syncthreads();
    for (int idx = tid; idx < KD_ * H_; idx += 256)
        pooled[idx] = pooled[idx] / Zs[idx & (H_ - 1)];
    __syncthreads();

    const int o = tid;  // 256 threads == OUT_
    float a = bias[o];
    const float4* Wr = reinterpret_cast<const float4*>(W + (size_t)o * (KD_ * H_));
#pragma unroll 8
    for (int i = 0; i < (KD_ * H_) / 4; i++) {
        float4 wv = Wr[i];
        a = fmaf(wv.x, pooled[i * 4 + 0],
            fmaf(wv.y, pooled[i * 4 + 1],
            fmaf(wv.z, pooled[i * 4 + 2],
            fmaf(wv.w, pooled[i * 4 + 3], a))));
    }
    const float e = emb[(size_t)num[b] * OUT_ + o];
    a += fmaxf(e, 0.f);
    out[(size_t)b * OUT_ + o] = fmaxf(a, 0.f);
}

// ---------------------------------------------------------------------------
// Launch
// Inputs (metadata order): x, mask, num, queries, W, b, emb
// ---------------------------------------------------------------------------
extern "C" void kernel_launch(void* const* d_in, const int* in_sizes, int n_in,
                              void* d_out, int out_size)
{
    const float* x    = (const float*)d_in[0];
    const int*   mask = (const int*)d_in[1];     // bool -> int32 on upload
    const int*   num  = (const int*)d_in[2];
    const float* q    = (const float*)d_in[3];
    const float* W    = (const float*)d_in[4];
    const float* bias = (const float*)d_in[5];
    const float* emb  = (const float*)d_in[6];
    float*       out  = (float*)d_out;

    pool_pass1<<<NBLK1, 256>>>(x, mask, q);
    pool_pass2<<<B_, 256>>>(W, bias, emb, num, out);
}

// round 4
// speedup vs baseline: 1.5762x; 1.5762x over previous
#include <cuda_runtime.h>
#include <cuda_bf16.h>
#include <cstdint>

// Problem constants
#define B_   64
#define L_   4096
#define KD_  128
#define H_   4
#define OUT_ 256

#define CHUNKS 16                // L-chunks per batch
#define WARPS  4                 // warps per block in pass 1 (128 threads)
#define ROWS_PER_WARP (L_ / CHUNKS / WARPS)   // 64
#define NBLK1 (B_ * CHUNKS)      // 1024
#define OGROUPS 8                // pass-2 output groups (32 outputs each)

// Deterministic scratch (no device allocation allowed)
__device__ float g_pacc[NBLK1][KD_ * H_];  // 1024 x 512 f32 = 2 MB
__device__ float g_pZ[NBLK1][H_];

__device__ __forceinline__ float warp_sum32(float v) {
#pragma unroll
    for (int off = 16; off >= 1; off >>= 1)
        v += __shfl_xor_sync(0xffffffffu, v, off);
    return v;
}

// ---------------------------------------------------------------------------
// Pass 1: streaming attention-pool partials.
// Mask -> 64-bit bitmap (2 ballots). Only live rows processed, 2 per
// iteration. Paired-half reduction: one offset-16 exchange splits row A into
// lanes 0-15 / row B into lanes 16-31, then 4 butterfly levels reduce BOTH
// rows at once; one more exchange returns both rows' softmax weights.
// 24 SHFL + 4 MUFU per 2 rows (vs 40 SHFL + 8 MUFU naive).
// exp(-1e9)==0 in fp32 => skipping masked rows is exact. |score|<~4 => no
// max subtraction needed.
// ---------------------------------------------------------------------------
__global__ void __launch_bounds__(128, 8)
pool_pass1(const float* __restrict__ x,
           const int* __restrict__ mask,   // bool coerced to int32 by harness
           const float* __restrict__ q)
{
    const int blk  = blockIdx.x;
    const int b    = blk / CHUNKS;
    const int c    = blk % CHUNKS;
    const int w    = threadIdx.x >> 5;
    const int lane = threadIdx.x & 31;
    const bool lo  = (lane < 16);

    // queries[h][lane*4 .. lane*4+3]
    float4 q4[H_];
#pragma unroll
    for (int h = 0; h < H_; h++)
        q4[h] = *reinterpret_cast<const float4*>(q + h * KD_ + lane * 4);

    float acc[4][H_];
#pragma unroll
    for (int j = 0; j < 4; j++)
#pragma unroll
        for (int h = 0; h < H_; h++) acc[j][h] = 0.0f;
    float Z[H_] = {0.f, 0.f, 0.f, 0.f};

    const int l0 = c * (L_ / CHUNKS) + w * ROWS_PER_WARP;
    const float* xb = x + (size_t)b * L_ * KD_ + (size_t)l0 * KD_;
    const int* mb = mask + (size_t)b * L_ + l0;

    // Compress this warp's 64 mask words into one 64-bit bitmap.
    const unsigned m_lo = __ballot_sync(0xffffffffu, mb[lane] != 0);
    const unsigned m_hi = __ballot_sync(0xffffffffu, mb[32 + lane] != 0);
    unsigned long long bits = ((unsigned long long)m_hi << 32) | (unsigned long long)m_lo;

    while (bits) {
        const int rA = __ffsll((long long)bits) - 1;
        bits &= bits - 1;
        int rB; float wB;
        if (bits) { rB = __ffsll((long long)bits) - 1; bits &= bits - 1; wB = 1.0f; }
        else      { rB = rA; wB = 0.0f; }   // duplicate row, zero-weighted

        const float4 xvA = *reinterpret_cast<const float4*>(xb + (size_t)rA * KD_ + lane * 4);
        const float4 xvB = *reinterpret_cast<const float4*>(xb + (size_t)rB * KD_ + lane * 4);

        float s0[H_], s1[H_];
#pragma unroll
        for (int h = 0; h < H_; h++) {
            s0[h] = xvA.x * q4[h].x + xvA.y * q4[h].y + xvA.z * q4[h].z + xvA.w * q4[h].w;
            s1[h] = xvB.x * q4[h].x + xvB.y * q4[h].y + xvB.z * q4[h].z + xvB.w * q4[h].w;
        }

        // Level-16 pairing: fold rows into opposite halves.
        float t[H_];
#pragma unroll
        for (int h = 0; h < H_; h++) {
            const float send = lo ? s1[h] : s0[h];
            const float recv = __shfl_xor_sync(0xffffffffu, send, 16);
            t[h] = (lo ? s0[h] : s1[h]) + recv;
        }
        // 4 more levels reduce both rows simultaneously (within halves).
#pragma unroll
        for (int off = 8; off >= 1; off >>= 1)
#pragma unroll
            for (int h = 0; h < H_; h++)
                t[h] += __shfl_xor_sync(0xffffffffu, t[h], off);

        // lanes 0-15 hold S_A[h]; lanes 16-31 hold S_B[h]. Each lane exps its row.
        const float wSelf = lo ? 1.0f : wB;
        float e[H_];
#pragma unroll
        for (int h = 0; h < H_; h++) e[h] = __expf(t[h]) * wSelf;

        // Exchange to give every lane both rows' weights.
        float pA[H_], pB[H_];
#pragma unroll
        for (int h = 0; h < H_; h++) {
            const float o = __shfl_xor_sync(0xffffffffu, e[h], 16);
            pA[h] = lo ? e[h] : o;
            pB[h] = lo ? o : e[h];
            Z[h] += pA[h] + pB[h];
        }

        const float xaj[4] = {xvA.x, xvA.y, xvA.z, xvA.w};
        const float xbj[4] = {xvB.x, xvB.y, xvB.z, xvB.w};
#pragma unroll
        for (int j = 0; j < 4; j++)
#pragma unroll
            for (int h = 0; h < H_; h++)
                acc[j][h] = fmaf(xaj[j], pA[h], fmaf(xbj[j], pB[h], acc[j][h]));
    }

    // Block-level deterministic reduce
    __shared__ float sAcc[WARPS][KD_ * H_];
    __shared__ float sZ[WARPS][H_];
#pragma unroll
    for (int j = 0; j < 4; j++)
#pragma unroll
        for (int h = 0; h < H_; h++)
            sAcc[w][(lane * 4 + j) * H_ + h] = acc[j][h];   // idx = k*H + h
    if (lane < H_) sZ[w][lane] = Z[lane];
    __syncthreads();

    for (int idx = threadIdx.x; idx < KD_ * H_; idx += 128) {
        float v = 0.f;
#pragma unroll
        for (int ww = 0; ww < WARPS; ww++) v += sAcc[ww][idx];
        g_pacc[blk][idx] = v;
    }
    if (threadIdx.x < H_) {
        float v = 0.f;
#pragma unroll
        for (int ww = 0; ww < WARPS; ww++) v += sZ[ww][threadIdx.x];
        g_pZ[blk][threadIdx.x] = v;
    }
}

// ---------------------------------------------------------------------------
// Pass 2: combine chunk partials -> pooled, then
//   out = relu(pooled @ W^T + b + relu(emb[num]))
// Grid = B * OGROUPS blocks; each block = one batch x 32 outputs.
// Each warp computes 4 outputs with lane-parallel dots.
// ---------------------------------------------------------------------------
__global__ void __launch_bounds__(256, 4)
pool_pass2(const float* __restrict__ W,
           const float* __restrict__ bias,
           const float* __restrict__ emb,
           const int* __restrict__ num,
           float* __restrict__ out)
{
    const int bg  = blockIdx.x;
    const int b   = bg / OGROUPS;
    const int g   = bg % OGROUPS;
    const int tid = threadIdx.x;

    __shared__ float pooled[KD_ * H_];
    __shared__ float Zs[H_];

    if (tid < H_) {
        float v = 0.f;
#pragma unroll
        for (int c = 0; c < CHUNKS; c++) v += g_pZ[b * CHUNKS + c][tid];
        Zs[tid] = v;
    }
    for (int idx = tid; idx < KD_ * H_; idx += 256) {
        float v = 0.f;
#pragma unroll
        for (int c = 0; c < CHUNKS; c++) v += g_pacc[b * CHUNKS + c][idx];
        pooled[idx] = v;
    }
    __syncthreads();
    for (int idx = tid; idx < KD_ * H_; idx += 256)
        pooled[idx] = pooled[idx] / Zs[idx & (H_ - 1)];
    __syncthreads();

    const int wrp  = tid >> 5;
    const int lane = tid & 31;
    const int o0   = g * 32 + wrp * 4;          // 4 outputs per warp

    float a[4];
#pragma unroll
    for (int j = 0; j < 4; j++) {
        const float* Wr = W + (size_t)(o0 + j) * (KD_ * H_);
        float s = 0.f;
#pragma unroll
        for (int q4i = 0; q4i < 4; q4i++) {
            const float4 wv = *reinterpret_cast<const float4*>(Wr + q4i * 128 + lane * 4);
            const float4 pv = *reinterpret_cast<const float4*>(&pooled[q4i * 128 + lane * 4]);
            s = fmaf(wv.x, pv.x, fmaf(wv.y, pv.y, fmaf(wv.z, pv.z, fmaf(wv.w, pv.w, s))));
        }
        a[j] = warp_sum32(s);
    }

    if (lane == 0) {
        const int nb = num[b];
#pragma unroll
        for (int j = 0; j < 4; j++) {
            const int o = o0 + j;
            float v = a[j] + bias[o] + fmaxf(emb[(size_t)nb * OUT_ + o], 0.f);
            out[(size_t)b * OUT_ + o] = fmaxf(v, 0.f);
        }
    }
}

// ---------------------------------------------------------------------------
// Launch.  Inputs (metadata order): x, mask, num, queries, W, b, emb
// ---------------------------------------------------------------------------
extern "C" void kernel_launch(void* const* d_in, const int* in_sizes, int n_in,
                              void* d_out, int out_size)
{
    const float* x    = (const float*)d_in[0];
    const int*   mask = (const int*)d_in[1];     // bool -> int32 on upload
    const int*   num  = (const int*)d_in[2];
    const float* q    = (const float*)d_in[3];
    const float* W    = (const float*)d_in[4];
    const float* bias = (const float*)d_in[5];
    const float* emb  = (const float*)d_in[6];
    float*       out  = (float*)d_out;

    pool_pass1<<<NBLK1, 128>>>(x, mask, q);
    pool_pass2<<<B_ * OGROUPS, 256>>>(W, bias, emb, num, out);
}